// round 10
// baseline (speedup 1.0000x reference)
#include <cuda_runtime.h>
#include <math.h>

// Problem constants (match reference)
#define T_STEPS 1024
#define B_SIZE  32768
#define G1      50
#define H1      32
#define G2      20
#define NBLOCKS 512
#define NCH     4
#define CH_T    (T_STEPS / NCH)        // 256 steps per chunk
#define PROD_PER_CH (NBLOCKS / NCH)    // 128 producer blocks per chunk

// Device globals (zero-initialized at load; NEVER reset — epoch-monotonic)
__device__ float        g_cbeta[T_STEPS];
__device__ unsigned int g_cnt [NCH * 32];      // arrival counters, 128B apart
__device__ unsigned int g_flag[NCH * 32];      // epoch-valued ready flags
__device__ unsigned int g_blkepoch[NBLOCKS];   // per-block launch epoch

// ---------------------------------------------------------------------------
// Fused pipelined kernel, epoch-synchronized (no reset machinery at all).
//  Epoch: e = ++g_blkepoch[bid] (owner-only RMW, race-free; all blocks get
//  the same e each launch since every launch runs every block once).
//  Producers: block b computes betas 2b,2b+1 (warp-parallel factorized KAN),
//  fences, bumps chunk counter (b>>7); the 128th arriver publishes
//  flag[c] = e. Stale flags hold e-1 -> consumers can never pass early.
//  Consumers: before scanning chunk c, wait flag[c]==e. Chunk 0 is produced
//  by the first-dispatched 128 blocks (~2-3us); chunks 1-3 are ready ~20us
//  before consumption -> effectively one exposed wait.
// Residency: 512 blocks x 64 thr, ~1.6KB smem, ~40 regs -> whole grid in one
// wave (4 blocks/SM needed, limit >20), so spins cannot deadlock. No block
// waits before producing.
// ---------------------------------------------------------------------------
__global__ void __launch_bounds__(64)
fused_kan_sir_kernel(const float* __restrict__ t_steps,
                     const float* __restrict__ initial_I,
                     const float* __restrict__ grid1,
                     const float* __restrict__ spline_w1, // [50,32]
                     const float* __restrict__ base_w1,   // [32]
                     const float* __restrict__ grid2,
                     const float* __restrict__ spline_w2, // [32,20]
                     const float* __restrict__ base_w2,   // [32]
                     const float* __restrict__ gamma_param,
                     float* __restrict__ out)
{
    __shared__ float        sbasis[2][G1];   // per-warp layer-1 basis
    __shared__ float        C2[G2];
    __shared__ float        sc[CH_T + 2];    // current beta chunk + sentinel
    __shared__ unsigned int sepoch;

    const int tid  = threadIdx.x;
    const int w    = tid >> 5;
    const int lane = tid & 31;

    // ---- Epoch bump (owner-only; no races) ----
    if (tid == 0) {
        unsigned int e = g_blkepoch[blockIdx.x] + 1u;
        g_blkepoch[blockIdx.x] = e;
        sepoch = e;
    }

    // ---- Prefetch scan inputs (latency hides under phase 1) ----
    const int   b      = blockIdx.x * 64 + tid;
    const float I_init = initial_I[b];
    const float gp     = gamma_param[0];
    const float dt     = t_steps[1] - t_steps[0];

    // ---- Phase 1: beta(t), t = 2*bid + w, one warp per t ----
    {
        const int   t = blockIdx.x * 2 + w;
        const float x = t_steps[t];

        {   // layer-1 basis: 50 exps per warp
            float d = x - grid1[lane];
            sbasis[w][lane] = __expf(-10.0f * d * d);
            if (lane < G1 - 32) {
                float d2 = x - grid1[lane + 32];
                sbasis[w][lane + 32] = __expf(-10.0f * d2 * d2);
            }
        }
        if (lane < G2) {    // both warps write identical values — benign
            float v = grid2[lane] - 0.5f;
            C2[lane] = __expf(-10.0f * v * v);
        }
        __syncwarp();

        // h[lane] = x*base_w1 + sum_g basis[g]*w1[g][lane]
        float acc0 = x * base_w1[lane];
        float acc1 = 0.0f;
        #pragma unroll
        for (int g = 0; g < G1 - 1; g += 2) {
            acc0 = fmaf(sbasis[w][g],     spline_w1[g * H1 + lane],       acc0);
            acc1 = fmaf(sbasis[w][g + 1], spline_w1[(g + 1) * H1 + lane], acc1);
        }
        const float h = fmaf(sbasis[w][G1 - 1], spline_w1[(G1 - 1) * H1 + lane],
                             acc0 + acc1);

        // layer-2 factorized RBF (3 exps instead of 20)
        float u = fminf(fmaxf(h - 0.5f, -2.5f), 2.5f);  // clamp: basis ~0 there
        const float v0 = grid2[0] - 0.5f;
        const float dv = grid2[1] - grid2[0];
        const float e0 = __expf(-10.0f * u * u);
        float       tk = __expf(20.0f * u * v0);
        const float f  = __expf(20.0f * u * dv);

        float acc = 0.0f;
        #pragma unroll
        for (int k = 0; k < G2; k++) {
            acc = fmaf(tk * C2[k], spline_w2[lane * G2 + k], acc);
            tk *= f;
        }
        acc = fmaf(h, base_w2[lane], e0 * acc);

        #pragma unroll
        for (int o = 16; o > 0; o >>= 1)
            acc += __shfl_down_sync(0xFFFFFFFFu, acc, o);

        if (lane == 0) {
            float beta = fmaxf(acc, 0.0f) + log1pf(expf(-fabsf(acc)));
            g_cbeta[t] = dt * beta;
        }
    }
    __syncthreads();
    const unsigned int e = sepoch;

    // ---- Producer arrival: bump chunk counter; 128th sets epoch flag ----
    if (tid == 0) {
        const int c = blockIdx.x >> 7;          // my chunk
        __threadfence();                        // publish my betas
        unsigned int ret = atomicAdd(&g_cnt[c * 32], 1u);
        if ((ret & (PROD_PER_CH - 1u)) == PROD_PER_CH - 1u) {
            __threadfence();                    // order after counter observe
            *((volatile unsigned int*)&g_flag[c * 32]) = e;
        }
    }

    // ---- Phase 2: chunked scan ----
    float I = I_init;
    float S = 1.0f - I;
    const float gamma = fmaxf(gp, 0.0f) + log1pf(expf(-fabsf(gp)));
    const float a     = 1.0f - dt * gamma;

    float* outp = out + b;

    #pragma unroll 1
    for (int c = 0; c < NCH; c++) {
        if (tid == 0) {
            while (*((volatile unsigned int*)&g_flag[c * 32]) != e) { }
            __threadfence();
        }
        __syncthreads();
        #pragma unroll
        for (int k = 0; k < CH_T / 64; k++)
            sc[tid + k * 64] = __ldcg(&g_cbeta[c * CH_T + tid + k * 64]);
        if (tid == 0) sc[CH_T] = 0.0f;          // prefetch sentinel
        __syncthreads();

        float* op = outp + (size_t)c * CH_T * B_SIZE;
        float cb = sc[0];
        #pragma unroll 8
        for (int u = 0; u < CH_T; u++) {
            const float cbn = sc[u + 1];        // prefetch next beta
            const float ni = cb * (S * I);      // dt * new_infections
            I = fmaf(I, a, ni);                 // clips removed: state in [0,1]
            S = S - ni;
            op[(size_t)u * B_SIZE] = I;
            cb = cbn;
        }
        __syncthreads();                        // sc reused next chunk
    }
}

// ---------------------------------------------------------------------------
// Inputs (metadata order):
// 0: t_steps [1024], 1: initial_I [32768], 2: grid1 [50], 3: spline_w1 [1600],
// 4: base_w1 [32], 5: grid2 [20], 6: spline_w2 [640], 7: base_w2 [32],
// 8: gamma_param [1]
// ---------------------------------------------------------------------------
extern "C" void kernel_launch(void* const* d_in, const int* in_sizes, int n_in,
                              void* d_out, int out_size)
{
    const float* t_steps    = (const float*)d_in[0];
    const float* initial_I  = (const float*)d_in[1];
    const float* grid1      = (const float*)d_in[2];
    const float* spline_w1  = (const float*)d_in[3];
    const float* base_w1    = (const float*)d_in[4];
    const float* grid2      = (const float*)d_in[5];
    const float* spline_w2  = (const float*)d_in[6];
    const float* base_w2    = (const float*)d_in[7];
    const float* gamma_p    = (const float*)d_in[8];
    float* out              = (float*)d_out;

    fused_kan_sir_kernel<<<NBLOCKS, 64>>>(t_steps, initial_I, grid1,
                                          spline_w1, base_w1, grid2,
                                          spline_w2, base_w2, gamma_p, out);
}

// round 11
// speedup vs baseline: 1.0548x; 1.0548x over previous
#include <cuda_runtime.h>
#include <math.h>

// Problem constants (match reference)
#define T_STEPS 1024
#define B_SIZE  32768
#define G1      50
#define H1      32
#define G2      20
#define KAN_WARPS 8                 // betas per block
#define KAN_BLOCKS (T_STEPS / KAN_WARPS)   // 128 — one block per SM

// Scratch: dt * beta[t] (device global — no allocation allowed)
__device__ float g_cbeta[T_STEPS];

// ---------------------------------------------------------------------------
// Kernel 1: cbeta[t] = dt * softplus(KAN2(KAN1(t/T))).
// Warp-per-beta: 128 blocks x 8 warps, each warp computes one t fully
// warp-locally (per-warp smem slices, __syncwarp only — NO block syncs).
// Layer-2 RBF factorized (3 exps per (t,i) instead of 20).
// ---------------------------------------------------------------------------
__global__ void __launch_bounds__(256)
kan_beta_kernel(const float* __restrict__ t_steps,
                const float* __restrict__ grid1,
                const float* __restrict__ spline_w1, // [50,32]
                const float* __restrict__ base_w1,   // [32]
                const float* __restrict__ grid2,
                const float* __restrict__ spline_w2, // [32,20]
                const float* __restrict__ base_w2)   // [32]
{
    __shared__ float sbasis[KAN_WARPS][G1 + 2];   // per-warp layer-1 basis
    __shared__ float sC2[KAN_WARPS][G2];          // per-warp C2 table

    const int w    = threadIdx.x >> 5;
    const int lane = threadIdx.x & 31;
    const int t    = blockIdx.x * KAN_WARPS + w;

    const float x  = t_steps[t];
    const float dt = t_steps[1] - t_steps[0];

    // Layer-1 basis: 50 exps per warp (lanes 0..17 do two)
    {
        float d = x - grid1[lane];
        sbasis[w][lane] = __expf(-10.0f * d * d);
        if (lane < G1 - 32) {
            float d2 = x - grid1[lane + 32];
            sbasis[w][lane + 32] = __expf(-10.0f * d2 * d2);
        }
    }
    // C2[k] = exp(-10*(grid2[k]-0.5)^2), per-warp copy (no block sync needed)
    if (lane < G2) {
        float v = grid2[lane] - 0.5f;
        sC2[w][lane] = __expf(-10.0f * v * v);
    }
    __syncwarp();

    // h[lane] = x*base_w1[lane] + sum_g basis[g]*w1[g][lane]  (split chains)
    float acc0 = x * base_w1[lane];
    float acc1 = 0.0f;
    #pragma unroll
    for (int g = 0; g < G1 - 1; g += 2) {
        acc0 = fmaf(sbasis[w][g],     spline_w1[g * H1 + lane],       acc0);
        acc1 = fmaf(sbasis[w][g + 1], spline_w1[(g + 1) * H1 + lane], acc1);
    }
    const float h = fmaf(sbasis[w][G1 - 1], spline_w1[(G1 - 1) * H1 + lane],
                         acc0 + acc1);

    // Layer-2 factorized RBF: exp(-10(h-g_k)^2) = e0 * tk * C2[k],
    // tk a geometric running product — 3 exps instead of 20.
    float u = fminf(fmaxf(h - 0.5f, -2.5f), 2.5f);   // clamp: basis ~0 there
    const float v0 = grid2[0] - 0.5f;
    const float dv = grid2[1] - grid2[0];
    const float e0 = __expf(-10.0f * u * u);
    float       tk = __expf(20.0f * u * v0);
    const float f  = __expf(20.0f * u * dv);

    float acc = 0.0f;
    #pragma unroll
    for (int k = 0; k < G2; k++) {
        acc = fmaf(tk * sC2[w][k], spline_w2[lane * G2 + k], acc);
        tk *= f;
    }
    acc = fmaf(h, base_w2[lane], e0 * acc);

    // warp reduce 32 -> 1
    #pragma unroll
    for (int o = 16; o > 0; o >>= 1)
        acc += __shfl_down_sync(0xFFFFFFFFu, acc, o);

    if (lane == 0) {
        float beta = fmaxf(acc, 0.0f) + log1pf(expf(-fabsf(acc)));  // softplus
        g_cbeta[t] = dt * beta;
    }
}

// ---------------------------------------------------------------------------
// Kernel 2: Euler SIR scan — one thread per batch element (proven-optimal
// 512x64 config, 24.5us = DRAM-write roofline). Clips removed: state
// provably stays in [0,1] (verified bit-stable since R4).
// ---------------------------------------------------------------------------
__global__ void __launch_bounds__(64)
sir_scan_kernel(const float* __restrict__ initial_I,
                const float* __restrict__ t_steps,
                const float* __restrict__ gamma_param,
                float* __restrict__ out)
{
    __shared__ float scb[T_STEPS + 8];   // padded: t+1 prefetch never guards
    #pragma unroll
    for (int i = 0; i < T_STEPS / 64; i++)
        scb[threadIdx.x + i * 64] = g_cbeta[threadIdx.x + i * 64];
    if (threadIdx.x < 8) scb[T_STEPS + threadIdx.x] = 0.0f;

    const int b = blockIdx.x * 64 + threadIdx.x;

    float I = initial_I[b];
    float S = 1.0f - I;

    const float gp    = gamma_param[0];
    const float gamma = fmaxf(gp, 0.0f) + log1pf(expf(-fabsf(gp)));
    const float dt    = t_steps[1] - t_steps[0];
    const float a     = 1.0f - dt * gamma;   // I' = I*a + ni

    __syncthreads();

    float* outp = out + b;
    float cb = scb[0];
    #pragma unroll 8
    for (int t = 0; t < T_STEPS; t++) {
        const float cb_n = scb[t + 1];       // prefetch next beta
        const float ni = cb * (S * I);       // dt * new_infections
        I = fmaf(I, a, ni);
        S = S - ni;
        outp[(size_t)t * B_SIZE] = I;
        cb = cb_n;
    }
}

// ---------------------------------------------------------------------------
// Inputs (metadata order):
// 0: t_steps [1024], 1: initial_I [32768], 2: grid1 [50], 3: spline_w1 [1600],
// 4: base_w1 [32], 5: grid2 [20], 6: spline_w2 [640], 7: base_w2 [32],
// 8: gamma_param [1]
// ---------------------------------------------------------------------------
extern "C" void kernel_launch(void* const* d_in, const int* in_sizes, int n_in,
                              void* d_out, int out_size)
{
    const float* t_steps    = (const float*)d_in[0];
    const float* initial_I  = (const float*)d_in[1];
    const float* grid1      = (const float*)d_in[2];
    const float* spline_w1  = (const float*)d_in[3];
    const float* base_w1    = (const float*)d_in[4];
    const float* grid2      = (const float*)d_in[5];
    const float* spline_w2  = (const float*)d_in[6];
    const float* base_w2    = (const float*)d_in[7];
    const float* gamma_p    = (const float*)d_in[8];
    float* out              = (float*)d_out;

    kan_beta_kernel<<<KAN_BLOCKS, 256>>>(t_steps, grid1, spline_w1, base_w1,
                                         grid2, spline_w2, base_w2);
    sir_scan_kernel<<<B_SIZE / 64, 64>>>(initial_I, t_steps, gamma_p, out);
}